// round 12
// baseline (speedup 1.0000x reference)
#include <cuda_runtime.h>

#define TT 1024
#define BB 512
#define DD 128
#define NO 11                 // 0=f,1=i,2=o,3..10=g0..g7
#define PSTR (NO*BB)
#define PREPB 256             // prep blocks (128 thr), REPS timesteps each
#define REPS 4
#define RECB 16               // recur blocks: 128 thr = 4 warps, 32 batch each

__device__ float g_pre[TT * NO * BB];     // ~23 MB scratch, [t][k][B]
__device__ unsigned g_ready[TT];          // zero-init at load; monotonic flags

__device__ __forceinline__ float f4c(const float4 v, int kk){
    return kk==0 ? v.x : kk==1 ? v.y : kk==2 ? v.z : v.w;
}

__device__ __forceinline__ float tanh_fast(float v){
    return 1.0f - __fdividef(2.0f, __expf(2.0f*v) + 1.0f);
}

// sigmoid(u), u in [-1,1]: 0.5 + u*P(u^2), Estrin, |err| ~ 2e-7
__device__ __forceinline__ float sigm_poly(float u){
    const float t  = u*u;
    const float E0 = fmaf(t, -2.0833334e-2f, 0.25f);
    const float E1 = fmaf(t, -2.10821e-4f,   2.0833334e-3f);
    const float E2 = fmaf(t, -2.16387e-6f,   2.13570e-5f);
    const float t2 = t*t;
    const float P  = fmaf(t2, fmaf(t2, E2, E1), E0);
    return fmaf(u, P, 0.5f);
}

__device__ __forceinline__ unsigned flag_acq(const unsigned* fp){
    unsigned v;
    asm volatile("ld.acquire.gpu.global.b32 %0, [%1];"
                 : "=r"(v) : "l"(fp) : "memory");
    return v;
}

__global__ void __launch_bounds__(128) fused_kernel(
    const float* __restrict__ x,
    const float* __restrict__ Wf, const float* __restrict__ bf,
    const float* __restrict__ Wi, const float* __restrict__ bi,
    const float* __restrict__ Wu, const float* __restrict__ bu,
    const float* __restrict__ Wo, const float* __restrict__ bo,
    const float* __restrict__ qwf, const float* __restrict__ qwi,
    const float* __restrict__ qwo,
    float* __restrict__ out, int write_tail)
{
    const int bid = blockIdx.x;
    const int tid = threadIdx.x;

    if (bid < PREPB){
        // ================= PREP ROLE (proven, unchanged) =================
        __shared__ __align__(16) float wsm[DD*12];
        __shared__ float bsm[12];
        {
            const int k = tid;
            wsm[k*12+0] = Wf[k];
            wsm[k*12+1] = Wi[k];
            wsm[k*12+2] = Wo[k];
#pragma unroll
            for (int u = 0; u < 8; u++) wsm[k*12+3+u] = Wu[u*136 + k];
            wsm[k*12+11] = 0.0f;
            if (tid == 0){
                bsm[0] = bf[0]; bsm[1] = bi[0]; bsm[2] = bo[0];
                for (int u = 0; u < 8; u++) bsm[3+u] = bu[u];
                bsm[11] = 0.0f;
            }
        }
        __syncthreads();

        for (int rep = 0; rep < REPS; rep++){
            const int t = bid + rep*PREPB;          // low t finish first
            const float4* __restrict__ xp =
                (const float4*)x + ((long long)t*BB + tid*4)*(DD/4);

            float acc[4][NO];
#pragma unroll
            for (int r = 0; r < 4; r++)
#pragma unroll
                for (int j = 0; j < NO; j++) acc[r][j] = bsm[j];

#pragma unroll 2
            for (int c = 0; c < 32; c++){
                float4 xv[4];
#pragma unroll
                for (int r = 0; r < 4; r++) xv[r] = xp[r*32 + c];
#pragma unroll
                for (int kk = 0; kk < 4; kk++){
                    const int k = c*4 + kk;
                    const float4* wr = (const float4*)&wsm[k*12];
                    const float4 wa = wr[0], wb = wr[1], wc = wr[2];
                    const float w[NO] = {wa.x,wa.y,wa.z,wa.w,
                                         wb.x,wb.y,wb.z,wb.w,
                                         wc.x,wc.y,wc.z};
#pragma unroll
                    for (int r = 0; r < 4; r++){
                        const float xs = f4c(xv[r], kk);
#pragma unroll
                        for (int j = 0; j < NO; j++)
                            acc[r][j] = fmaf(xs, w[j], acc[r][j]);
                    }
                }
            }

            float* op = g_pre + (long long)t*PSTR + tid*4;
#pragma unroll
            for (int j = 0; j < NO; j++)
                *(float4*)(op + j*BB) =
                    make_float4(acc[0][j],acc[1][j],acc[2][j],acc[3][j]);

            __threadfence();
            __syncthreads();
            if (tid == 0)
                asm volatile("st.release.gpu.global.b32 [%0], %1;"
                             :: "l"(&g_ready[t]), "r"(1u) : "memory");
        }
        return;
    }

    // ================= RECUR ROLE =================
    // 16 blocks x 4 warps. 8 threads per batch element, one hidden lane each,
    // SMEM h-exchange (proven R11). NEW: each thread interleaves TWO
    // independent batch streams — their chains overlap, filling MUFU/sync
    // bubbles. Weights shared across streams.
    __shared__ __align__(16) float hxch[2][4][2][32]; // [buf][warp][stream][lane]

    const int rb   = bid - PREPB;
    const int lane = tid & 31;
    const int wrp  = tid >> 5;
    const int q    = lane & 7;                 // my hidden lane
    const int grp  = lane >> 3;                // my 8-lane group (0..3)
    const int bA   = rb*32 + wrp*8 + grp;      // stream A batch
    const int bB   = bA + 4;                   // stream B batch

    // Natural-order weights (uniform across lanes except wu8)
    float wf8[8], wi8[8], wo8[8], wu8[8];
#pragma unroll
    for (int r = 0; r < 8; r++){
        wf8[r] = Wf[DD + r];
        wi8[r] = Wi[DD + r];
        wo8[r] = Wo[DD + r];
        wu8[r] = Wu[q*136 + DD + r];           // my g row
    }
    const float cgf = cosf(qwf[0]);
    const float cgi = cosf(qwi[0]);
    const float cgo = cosf(qwo[0]);

    const float* __restrict__ preA = g_pre + bA;
    const float* __restrict__ preB = g_pre + bB;

    float hA = 0.f, cA = 0.f, hB = 0.f, cB = 0.f;
    float pr[4][2][4];                         // [phase][stream][f,i,o,g_q]

    const unsigned m = 0xffffffffu;

    float* slotA[2] = { &hxch[0][wrp][0][lane], &hxch[1][wrp][0][lane] };
    float* slotB[2] = { &hxch[0][wrp][1][lane], &hxch[1][wrp][1][lane] };
    const float4* rowA[2] = { (const float4*)&hxch[0][wrp][0][lane & 24],
                              (const float4*)&hxch[1][wrp][0][lane & 24] };
    const float4* rowB[2] = { (const float4*)&hxch[0][wrp][1][lane & 24],
                              (const float4*)&hxch[1][wrp][1][lane & 24] };

    auto FLAG_ADDR = [&](int tbase) -> const unsigned* {
        int tp = tbase + (lane & 3);
        if (tp > TT-1) tp = TT-1;
        return &g_ready[tp];
    };

    auto POLL_BLOCK = [&](int tbase){          // blocking (startup/slow path)
        const unsigned* fp = FLAG_ADDR(tbase);
        unsigned v;
        do { v = flag_acq(fp); } while (!__all_sync(m, v != 0));
    };

    auto LOAD = [&](float p[2][4], int t){
        const long long off = (long long)t*PSTR;
        const float* a = preA + off;
        const float* bp = preB + off;
        p[0][0] = __ldg(a);
        p[0][1] = __ldg(a + BB);
        p[0][2] = __ldg(a + 2*BB);
        p[0][3] = __ldg(a + (3 + q)*BB);
        p[1][0] = __ldg(bp);
        p[1][1] = __ldg(bp + BB);
        p[1][2] = __ldg(bp + 2*BB);
        p[1][3] = __ldg(bp + (3 + q)*BB);
    };

    auto STEP2 = [&](int t, const float p[2][4]){
        const int buf = t & 1;
        // exchange h for both streams through warp-private SMEM rows
        *slotA[buf] = hA;                      // STS
        *slotB[buf] = hB;                      // STS
        __syncwarp(m);
        const float4 Aa = rowA[buf][0];        // LDS.128 group-broadcast
        const float4 Ab = rowA[buf][1];
        const float4 Ba = rowB[buf][0];
        const float4 Bb = rowB[buf][1];
        const float HA[8] = {Aa.x,Aa.y,Aa.z,Aa.w, Ab.x,Ab.y,Ab.z,Ab.w};
        const float HB[8] = {Ba.x,Ba.y,Ba.z,Ba.w, Bb.x,Bb.y,Bb.z,Bb.w};

        // dots for both streams (dual accumulators each)
        float zfA_=p[0][0], ziA_=p[0][1], zoA_=p[0][2], zgA_=p[0][3];
        float zfB_=p[1][0], ziB_=p[1][1], zoB_=p[1][2], zgB_=p[1][3];
        float zfA2=0.f, ziA2=0.f, zoA2=0.f, zgA2=0.f;
        float zfB2=0.f, ziB2=0.f, zoB2=0.f, zgB2=0.f;
#pragma unroll
        for (int r = 0; r < 8; r += 2){
            zfA_ = fmaf(wf8[r],   HA[r],   zfA_);
            zfA2 = fmaf(wf8[r+1], HA[r+1], zfA2);
            ziA_ = fmaf(wi8[r],   HA[r],   ziA_);
            ziA2 = fmaf(wi8[r+1], HA[r+1], ziA2);
            zoA_ = fmaf(wo8[r],   HA[r],   zoA_);
            zoA2 = fmaf(wo8[r+1], HA[r+1], zoA2);
            zgA_ = fmaf(wu8[r],   HA[r],   zgA_);
            zgA2 = fmaf(wu8[r+1], HA[r+1], zgA2);
            zfB_ = fmaf(wf8[r],   HB[r],   zfB_);
            zfB2 = fmaf(wf8[r+1], HB[r+1], zfB2);
            ziB_ = fmaf(wi8[r],   HB[r],   ziB_);
            ziB2 = fmaf(wi8[r+1], HB[r+1], ziB2);
            zoB_ = fmaf(wo8[r],   HB[r],   zoB_);
            zoB2 = fmaf(wo8[r+1], HB[r+1], zoB2);
            zgB_ = fmaf(wu8[r],   HB[r],   zgB_);
            zgB2 = fmaf(wu8[r+1], HB[r+1], zgB2);
        }
        const float zfA = zfA_+zfA2, ziA = ziA_+ziA2;
        const float zoA = zoA_+zoA2, zgA = zgA_+zgA2;
        const float zfB = zfB_+zfB2, ziB = ziB_+ziB2;
        const float zoB = zoB_+zoB2, zgB = zgB_+zgB2;

        const float fA = sigm_poly(cgf * __cosf(zfA));
        const float fB = sigm_poly(cgf * __cosf(zfB));
        const float iA = sigm_poly(cgi * __cosf(ziA));
        const float iB = sigm_poly(cgi * __cosf(ziB));
        const float oA = sigm_poly(cgo * __cosf(zoA));
        const float oB = sigm_poly(cgo * __cosf(zoB));
        const float gA = tanh_fast(zgA);
        const float gB = tanh_fast(zgB);

        cA = fmaf(fA, cA, iA*gA);
        cB = fmaf(fB, cB, iB*gB);
        hA = oA * tanh_fast(cA);
        hB = oB * tanh_fast(cB);

        out[((long long)t*BB + bA)*8 + q] = hA;
        out[((long long)t*BB + bB)*8 + q] = hB;
    };

    // Startup: block on group 0..3, prime ring, prefetch flags for 4..7.
    POLL_BLOCK(0);
#pragma unroll
    for (int ph = 0; ph < 4; ph++) LOAD(pr[ph], ph);
    unsigned fv = flag_acq(FLAG_ADDR(4));

    for (int tb = 0; tb < TT; tb += 4){
        if (!__all_sync(m, fv != 0))
            POLL_BLOCK(tb + 4);                 // rare slow path
        fv = flag_acq(FLAG_ADDR(tb + 8));       // prefetch next group's flags
#pragma unroll
        for (int ph = 0; ph < 4; ph++){
            STEP2(tb + ph, pr[ph]);
            int tn = tb + ph + 4; if (tn >= TT) tn = TT - 1;
            LOAD(pr[ph], tn);
        }
    }

    if (write_tail){
        float* hp = out + (long long)TT*BB*8;
        hp[bA*8 + q]        = hA;
        hp[BB*8 + bA*8 + q] = cA;
        hp[bB*8 + q]        = hB;
        hp[BB*8 + bB*8 + q] = cB;
    }
}

// ---------------------------------------------------------------------------
extern "C" void kernel_launch(void* const* d_in, const int* in_sizes, int n_in,
                              void* d_out, int out_size)
{
    const float* x   = (const float*)d_in[0];
    const float* Wf  = (const float*)d_in[1];
    const float* bf  = (const float*)d_in[2];
    const float* Wi  = (const float*)d_in[3];
    const float* bi  = (const float*)d_in[4];
    const float* Wu  = (const float*)d_in[5];
    const float* bu  = (const float*)d_in[6];
    const float* Wo  = (const float*)d_in[7];
    const float* bo  = (const float*)d_in[8];
    const float* qwf = (const float*)d_in[9];
    const float* qwi = (const float*)d_in[10];
    // d_in[11] = qwu: unused — g path has no quantum gate in the reference
    const float* qwo = (const float*)d_in[12];
    float* out = (float*)d_out;

    const int write_tail = (out_size >= TT*BB*8 + 2*BB*8) ? 1 : 0;

    fused_kernel<<<PREPB + RECB, 128>>>(x, Wf, bf, Wi, bi, Wu, bu, Wo, bo,
                                        qwf, qwi, qwo, out, write_tail);
}

// round 13
// speedup vs baseline: 1.6163x; 1.6163x over previous
#include <cuda_runtime.h>

#define TT 1024
#define BB 512
#define DD 128
#define NO 11                 // 0=f,1=i,2=o,3..10=g0..g7
#define PSTR (NO*BB)
#define PREPB 256             // prep blocks (128 thr), REPS timesteps each
#define REPS 4
#define RECB 32               // recur blocks: 128 thr = 4 warps, 16 batch each

__device__ float g_pre[TT * NO * BB];     // ~23 MB scratch, [t][k][B]
__device__ unsigned g_ready[TT];          // zero-init at load; monotonic flags

__device__ __forceinline__ float f4c(const float4 v, int kk){
    return kk==0 ? v.x : kk==1 ? v.y : kk==2 ? v.z : v.w;
}

__device__ __forceinline__ float tanh_fast(float v){
    return 1.0f - __fdividef(2.0f, __expf(2.0f*v) + 1.0f);
}

// sigmoid(u), u in [-1,1]: 0.5 + u*P(u^2), Estrin, |err| ~ 2e-7
__device__ __forceinline__ float sigm_poly(float u){
    const float t  = u*u;
    const float E0 = fmaf(t, -2.0833334e-2f, 0.25f);
    const float E1 = fmaf(t, -2.10821e-4f,   2.0833334e-3f);
    const float E2 = fmaf(t, -2.16387e-6f,   2.13570e-5f);
    const float t2 = t*t;
    const float P  = fmaf(t2, fmaf(t2, E2, E1), E0);
    return fmaf(u, P, 0.5f);
}

__device__ __forceinline__ unsigned flag_acq(const unsigned* fp){
    unsigned v;
    asm volatile("ld.acquire.gpu.global.b32 %0, [%1];"
                 : "=r"(v) : "l"(fp) : "memory");
    return v;
}

__global__ void __launch_bounds__(128) fused_kernel(
    const float* __restrict__ x,
    const float* __restrict__ Wf, const float* __restrict__ bf,
    const float* __restrict__ Wi, const float* __restrict__ bi,
    const float* __restrict__ Wu, const float* __restrict__ bu,
    const float* __restrict__ Wo, const float* __restrict__ bo,
    const float* __restrict__ qwf, const float* __restrict__ qwi,
    const float* __restrict__ qwo,
    float* __restrict__ out, int write_tail)
{
    const int bid = blockIdx.x;
    const int tid = threadIdx.x;

    if (bid < PREPB){
        // ================= PREP ROLE (proven, unchanged) =================
        __shared__ __align__(16) float wsm[DD*12];
        __shared__ float bsm[12];
        {
            const int k = tid;
            wsm[k*12+0] = Wf[k];
            wsm[k*12+1] = Wi[k];
            wsm[k*12+2] = Wo[k];
#pragma unroll
            for (int u = 0; u < 8; u++) wsm[k*12+3+u] = Wu[u*136 + k];
            wsm[k*12+11] = 0.0f;
            if (tid == 0){
                bsm[0] = bf[0]; bsm[1] = bi[0]; bsm[2] = bo[0];
                for (int u = 0; u < 8; u++) bsm[3+u] = bu[u];
                bsm[11] = 0.0f;
            }
        }
        __syncthreads();

        for (int rep = 0; rep < REPS; rep++){
            const int t = bid + rep*PREPB;          // low t finish first
            const float4* __restrict__ xp =
                (const float4*)x + ((long long)t*BB + tid*4)*(DD/4);

            float acc[4][NO];
#pragma unroll
            for (int r = 0; r < 4; r++)
#pragma unroll
                for (int j = 0; j < NO; j++) acc[r][j] = bsm[j];

#pragma unroll 2
            for (int c = 0; c < 32; c++){
                float4 xv[4];
#pragma unroll
                for (int r = 0; r < 4; r++) xv[r] = xp[r*32 + c];
#pragma unroll
                for (int kk = 0; kk < 4; kk++){
                    const int k = c*4 + kk;
                    const float4* wr = (const float4*)&wsm[k*12];
                    const float4 wa = wr[0], wb = wr[1], wc = wr[2];
                    const float w[NO] = {wa.x,wa.y,wa.z,wa.w,
                                         wb.x,wb.y,wb.z,wb.w,
                                         wc.x,wc.y,wc.z};
#pragma unroll
                    for (int r = 0; r < 4; r++){
                        const float xs = f4c(xv[r], kk);
#pragma unroll
                        for (int j = 0; j < NO; j++)
                            acc[r][j] = fmaf(xs, w[j], acc[r][j]);
                    }
                }
            }

            float* op = g_pre + (long long)t*PSTR + tid*4;
#pragma unroll
            for (int j = 0; j < NO; j++)
                *(float4*)(op + j*BB) =
                    make_float4(acc[0][j],acc[1][j],acc[2][j],acc[3][j]);

            __threadfence();
            __syncthreads();
            if (tid == 0)
                asm volatile("st.release.gpu.global.b32 [%0], %1;"
                             :: "l"(&g_ready[t]), "r"(1u) : "memory");
        }
        return;
    }

    // ================= RECUR ROLE =================
    // 32 blocks x 4 warps. 8 threads per batch element, one hidden lane each,
    // SMEM h-exchange. CHANGE vs best (R11): the per-step __syncwarp is
    // removed — the warp is physically converged through the straight-line
    // STEP body, and same-warp smem ops complete in program order through
    // the MIO pipe, so STS -> LDS exchange is warp-synchronous. A compiler
    // memory barrier prevents reordering/hoisting.
    __shared__ __align__(16) float hxch[2][4][32];   // [buf][warp][lane]

    const int rb   = bid - PREPB;
    const int lane = tid & 31;
    const int wrp  = tid >> 5;
    const int q    = lane & 7;                 // my hidden lane
    const int b    = rb*16 + (tid >> 3);       // 16 batches per block

    // Natural-order weights (uniform across lanes except wu8)
    float wf8[8], wi8[8], wo8[8], wu8[8];
#pragma unroll
    for (int r = 0; r < 8; r++){
        wf8[r] = Wf[DD + r];
        wi8[r] = Wi[DD + r];
        wo8[r] = Wo[DD + r];
        wu8[r] = Wu[q*136 + DD + r];           // my g row
    }
    const float cgf = cosf(qwf[0]);
    const float cgi = cosf(qwi[0]);
    const float cgo = cosf(qwo[0]);

    const float* __restrict__ pre = g_pre + b;

    float h = 0.f, c = 0.f;
    float pr[8][4];                            // [phase][f,i,o,g_q]

    const unsigned m = 0xffffffffu;

    // SMEM exchange pointers
    float* slot[2] = { &hxch[0][wrp][lane],        &hxch[1][wrp][lane] };
    const float4* row[2] = {
        (const float4*)&hxch[0][wrp][lane & 24],   // my group's 8 h values
        (const float4*)&hxch[1][wrp][lane & 24]
    };

    auto FLAG_ADDR = [&](int tbase) -> const unsigned* {
        int tp = tbase + (lane & 7);
        if (tp > TT-1) tp = TT-1;
        return &g_ready[tp];
    };

    auto POLL_BLOCK = [&](int tbase){          // blocking (startup/slow path)
        const unsigned* fp = FLAG_ADDR(tbase);
        unsigned v;
        do { v = flag_acq(fp); } while (!__all_sync(m, v != 0));
    };

    auto LOAD = [&](float* p, int t){
        const float* base = pre + (long long)t*PSTR;
        p[0] = __ldg(base);                    // f pre-activation
        p[1] = __ldg(base + BB);               // i
        p[2] = __ldg(base + 2*BB);             // o
        p[3] = __ldg(base + (3 + q)*BB);       // my g row
    };

    auto STEP = [&](int t, const float* p){
        const int buf = t & 1;
        // h exchange through warp-private SMEM row — warp-synchronous
        *slot[buf] = h;                        // STS
        asm volatile("" ::: "memory");         // compiler barrier only
        const float4 Ha = row[buf][0];         // LDS.128 (broadcast in group)
        const float4 Hb = row[buf][1];
        const float H[8] = {Ha.x, Ha.y, Ha.z, Ha.w, Hb.x, Hb.y, Hb.z, Hb.w};

        // 4 local dots (f, i, o, my g), dual accumulators
        float zf = p[0], zi = p[1], zo = p[2], zg = p[3];
        float zfA = 0.f, ziA = 0.f, zoA = 0.f, zgA = 0.f;
#pragma unroll
        for (int r = 0; r < 8; r += 2){
            zf  = fmaf(wf8[r],   H[r],   zf );
            zfA = fmaf(wf8[r+1], H[r+1], zfA);
            zi  = fmaf(wi8[r],   H[r],   zi );
            ziA = fmaf(wi8[r+1], H[r+1], ziA);
            zo  = fmaf(wo8[r],   H[r],   zo );
            zoA = fmaf(wo8[r+1], H[r+1], zoA);
            zg  = fmaf(wu8[r],   H[r],   zg );
            zgA = fmaf(wu8[r+1], H[r+1], zgA);
        }
        zf += zfA; zi += ziA; zo += zoA; zg += zgA;

        const float f = sigm_poly(cgf * __cosf(zf));
        const float i = sigm_poly(cgi * __cosf(zi));
        const float o = sigm_poly(cgo * __cosf(zo));
        const float g = tanh_fast(zg);

        c = fmaf(f, c, i*g);
        h = o * tanh_fast(c);

        out[((long long)t*BB + b)*8 + q] = h;   // warp: 128B contiguous
    };

    // Startup: block on group 0, prime ring, prefetch flag for group 8.
    POLL_BLOCK(0);
#pragma unroll
    for (int ph = 0; ph < 8; ph++) LOAD(pr[ph], ph);
    unsigned fv = flag_acq(FLAG_ADDR(8));

    for (int tb = 0; tb < TT; tb += 8){
        if (!__all_sync(m, fv != 0))
            POLL_BLOCK(tb + 8);                 // rare slow path
        fv = flag_acq(FLAG_ADDR(tb + 16));      // prefetch next group's flags
#pragma unroll
        for (int ph = 0; ph < 8; ph++){
            STEP(tb + ph, pr[ph]);
            int tn = tb + ph + 8; if (tn >= TT) tn = TT - 1;
            LOAD(pr[ph], tn);
        }
    }

    if (write_tail){
        float* hp = out + (long long)TT*BB*8;
        hp[b*8 + q]         = h;
        hp[BB*8 + b*8 + q]  = c;
    }
}

// ---------------------------------------------------------------------------
extern "C" void kernel_launch(void* const* d_in, const int* in_sizes, int n_in,
                              void* d_out, int out_size)
{
    const float* x   = (const float*)d_in[0];
    const float* Wf  = (const float*)d_in[1];
    const float* bf  = (const float*)d_in[2];
    const float* Wi  = (const float*)d_in[3];
    const float* bi  = (const float*)d_in[4];
    const float* Wu  = (const float*)d_in[5];
    const float* bu  = (const float*)d_in[6];
    const float* Wo  = (const float*)d_in[7];
    const float* bo  = (const float*)d_in[8];
    const float* qwf = (const float*)d_in[9];
    const float* qwi = (const float*)d_in[10];
    // d_in[11] = qwu: unused — g path has no quantum gate in the reference
    const float* qwo = (const float*)d_in[12];
    float* out = (float*)d_out;

    const int write_tail = (out_size >= TT*BB*8 + 2*BB*8) ? 1 : 0;

    fused_kernel<<<PREPB + RECB, 128>>>(x, Wf, bf, Wi, bi, Wu, bu, Wo, bo,
                                        qwf, qwi, qwo, out, write_tail);
}

// round 14
// speedup vs baseline: 1.7738x; 1.0974x over previous
#include <cuda_runtime.h>

#define TT 1024
#define BB 512
#define DD 128
#define NO 11                 // 0=f,1=i,2=o,3..10=g0..g7
#define PSTR (NO*BB)
#define PREPB 116             // prep blocks (256 thr, 2 timesteps per rep)
#define RECB 32               // recur blocks: 128 thr = 4 warps, 16 batch each
// grid = 116 + 32 = 148 blocks = exactly one CTA per SM -> recur SMs are
// dedicated: no prep L1tex/issue contention.

__device__ float g_pre[TT * NO * BB];     // ~23 MB scratch, [t][k][B]
__device__ unsigned g_ready[TT];          // zero-init at load; monotonic flags

__device__ __forceinline__ float f4c(const float4 v, int kk){
    return kk==0 ? v.x : kk==1 ? v.y : kk==2 ? v.z : v.w;
}

__device__ __forceinline__ float tanh_fast(float v){
    return 1.0f - __fdividef(2.0f, __expf(2.0f*v) + 1.0f);
}

// sigmoid(u), u in [-1,1]: 0.5 + u*P(u^2), Estrin, |err| ~ 2e-7
__device__ __forceinline__ float sigm_poly(float u){
    const float t  = u*u;
    const float E0 = fmaf(t, -2.0833334e-2f, 0.25f);
    const float E1 = fmaf(t, -2.10821e-4f,   2.0833334e-3f);
    const float E2 = fmaf(t, -2.16387e-6f,   2.13570e-5f);
    const float t2 = t*t;
    const float P  = fmaf(t2, fmaf(t2, E2, E1), E0);
    return fmaf(u, P, 0.5f);
}

__device__ __forceinline__ unsigned flag_acq(const unsigned* fp){
    unsigned v;
    asm volatile("ld.acquire.gpu.global.b32 %0, [%1];"
                 : "=r"(v) : "l"(fp) : "memory");
    return v;
}

__global__ void __launch_bounds__(256) fused_kernel(
    const float* __restrict__ x,
    const float* __restrict__ Wf, const float* __restrict__ bf,
    const float* __restrict__ Wi, const float* __restrict__ bi,
    const float* __restrict__ Wu, const float* __restrict__ bu,
    const float* __restrict__ Wo, const float* __restrict__ bo,
    const float* __restrict__ qwf, const float* __restrict__ qwi,
    const float* __restrict__ qwo,
    float* __restrict__ out, int write_tail)
{
    const int bid = blockIdx.x;
    const int tid = threadIdx.x;

    if (bid < PREPB){
        // ================= PREP ROLE =================
        // 256 threads: lower 128 handle timestep t0, upper 128 handle t0+1.
        __shared__ __align__(16) float wsm[DD*12];
        __shared__ float bsm[12];
        {
            if (tid < DD){
                const int k = tid;
                wsm[k*12+0] = Wf[k];
                wsm[k*12+1] = Wi[k];
                wsm[k*12+2] = Wo[k];
#pragma unroll
                for (int u = 0; u < 8; u++) wsm[k*12+3+u] = Wu[u*136 + k];
                wsm[k*12+11] = 0.0f;
            }
            if (tid == 0){
                bsm[0] = bf[0]; bsm[1] = bi[0]; bsm[2] = bo[0];
                for (int u = 0; u < 8; u++) bsm[3+u] = bu[u];
                bsm[11] = 0.0f;
            }
        }
        __syncthreads();

        const int half = tid >> 7;              // which of the 2 timesteps
        const int lt   = tid & 127;             // thread within timestep

        for (int rep = 0; rep < 5; rep++){
            const int t0 = 2*(bid + rep*PREPB); // low t finish first
            if (t0 >= TT) break;
            const int t  = t0 + half;
            const float4* __restrict__ xp =
                (const float4*)x + ((long long)t*BB + lt*4)*(DD/4);

            float acc[4][NO];
#pragma unroll
            for (int r = 0; r < 4; r++)
#pragma unroll
                for (int j = 0; j < NO; j++) acc[r][j] = bsm[j];

#pragma unroll 2
            for (int c = 0; c < 32; c++){
                float4 xv[4];
#pragma unroll
                for (int r = 0; r < 4; r++) xv[r] = xp[r*32 + c];
#pragma unroll
                for (int kk = 0; kk < 4; kk++){
                    const int k = c*4 + kk;
                    const float4* wr = (const float4*)&wsm[k*12];
                    const float4 wa = wr[0], wb = wr[1], wc = wr[2];
                    const float w[NO] = {wa.x,wa.y,wa.z,wa.w,
                                         wb.x,wb.y,wb.z,wb.w,
                                         wc.x,wc.y,wc.z};
#pragma unroll
                    for (int r = 0; r < 4; r++){
                        const float xs = f4c(xv[r], kk);
#pragma unroll
                        for (int j = 0; j < NO; j++)
                            acc[r][j] = fmaf(xs, w[j], acc[r][j]);
                    }
                }
            }

            float* op = g_pre + (long long)t*PSTR + lt*4;
#pragma unroll
            for (int j = 0; j < NO; j++)
                *(float4*)(op + j*BB) =
                    make_float4(acc[0][j],acc[1][j],acc[2][j],acc[3][j]);

            __threadfence();
            __syncthreads();
            if (tid == 0){
                asm volatile("st.release.gpu.global.b32 [%0], %1;"
                             :: "l"(&g_ready[t0]),   "r"(1u) : "memory");
                asm volatile("st.release.gpu.global.b32 [%0], %1;"
                             :: "l"(&g_ready[t0+1]), "r"(1u) : "memory");
            }
        }
        return;
    }

    // ================= RECUR ROLE =================
    // 32 blocks x 4 warps, one block per SM, NO co-resident prep work.
    // 8 threads per batch element, one hidden lane each, SMEM h-exchange
    // (warp-synchronous, compiler-barrier only). Byte-identical STEP to best.
    if (tid >= 128) return;
    __shared__ __align__(16) float hxch[2][4][32];   // [buf][warp][lane]

    const int rb   = bid - PREPB;
    const int lane = tid & 31;
    const int wrp  = tid >> 5;
    const int q    = lane & 7;                 // my hidden lane
    const int b    = rb*16 + (tid >> 3);       // 16 batches per block

    // Natural-order weights (uniform across lanes except wu8)
    float wf8[8], wi8[8], wo8[8], wu8[8];
#pragma unroll
    for (int r = 0; r < 8; r++){
        wf8[r] = Wf[DD + r];
        wi8[r] = Wi[DD + r];
        wo8[r] = Wo[DD + r];
        wu8[r] = Wu[q*136 + DD + r];           // my g row
    }
    const float cgf = cosf(qwf[0]);
    const float cgi = cosf(qwi[0]);
    const float cgo = cosf(qwo[0]);

    const float* __restrict__ pre = g_pre + b;

    float h = 0.f, c = 0.f;
    float pr[8][4];                            // [phase][f,i,o,g_q]

    const unsigned m = 0xffffffffu;

    // SMEM exchange pointers
    float* slot[2] = { &hxch[0][wrp][lane],        &hxch[1][wrp][lane] };
    const float4* row[2] = {
        (const float4*)&hxch[0][wrp][lane & 24],   // my group's 8 h values
        (const float4*)&hxch[1][wrp][lane & 24]
    };

    auto FLAG_ADDR = [&](int tbase) -> const unsigned* {
        int tp = tbase + (lane & 7);
        if (tp > TT-1) tp = TT-1;
        return &g_ready[tp];
    };

    auto POLL_BLOCK = [&](int tbase){          // blocking (startup/slow path)
        const unsigned* fp = FLAG_ADDR(tbase);
        unsigned v;
        do { v = flag_acq(fp); } while (!__all_sync(m, v != 0));
    };

    auto LOAD = [&](float* p, int t){
        const float* base = pre + (long long)t*PSTR;
        p[0] = __ldg(base);                    // f pre-activation
        p[1] = __ldg(base + BB);               // i
        p[2] = __ldg(base + 2*BB);             // o
        p[3] = __ldg(base + (3 + q)*BB);       // my g row
    };

    auto STEP = [&](int t, const float* p){
        const int buf = t & 1;
        // h exchange through warp-private SMEM row — warp-synchronous
        *slot[buf] = h;                        // STS
        asm volatile("" ::: "memory");         // compiler barrier only
        const float4 Ha = row[buf][0];         // LDS.128 (broadcast in group)
        const float4 Hb = row[buf][1];
        const float H[8] = {Ha.x, Ha.y, Ha.z, Ha.w, Hb.x, Hb.y, Hb.z, Hb.w};

        // 4 local dots (f, i, o, my g), dual accumulators
        float zf = p[0], zi = p[1], zo = p[2], zg = p[3];
        float zfA = 0.f, ziA = 0.f, zoA = 0.f, zgA = 0.f;
#pragma unroll
        for (int r = 0; r < 8; r += 2){
            zf  = fmaf(wf8[r],   H[r],   zf );
            zfA = fmaf(wf8[r+1], H[r+1], zfA);
            zi  = fmaf(wi8[r],   H[r],   zi );
            ziA = fmaf(wi8[r+1], H[r+1], ziA);
            zo  = fmaf(wo8[r],   H[r],   zo );
            zoA = fmaf(wo8[r+1], H[r+1], zoA);
            zg  = fmaf(wu8[r],   H[r],   zg );
            zgA = fmaf(wu8[r+1], H[r+1], zgA);
        }
        zf += zfA; zi += ziA; zo += zoA; zg += zgA;

        const float f = sigm_poly(cgf * __cosf(zf));
        const float i = sigm_poly(cgi * __cosf(zi));
        const float o = sigm_poly(cgo * __cosf(zo));
        const float g = tanh_fast(zg);

        c = fmaf(f, c, i*g);
        h = o * tanh_fast(c);

        out[((long long)t*BB + b)*8 + q] = h;   // warp: 128B contiguous
    };

    // Startup: block on group 0, prime ring, prefetch flag for group 8.
    POLL_BLOCK(0);
#pragma unroll
    for (int ph = 0; ph < 8; ph++) LOAD(pr[ph], ph);
    unsigned fv = flag_acq(FLAG_ADDR(8));

    for (int tb = 0; tb < TT; tb += 8){
        if (!__all_sync(m, fv != 0))
            POLL_BLOCK(tb + 8);                 // rare slow path
        fv = flag_acq(FLAG_ADDR(tb + 16));      // prefetch next group's flags
#pragma unroll
        for (int ph = 0; ph < 8; ph++){
            STEP(tb + ph, pr[ph]);
            int tn = tb + ph + 8; if (tn >= TT) tn = TT - 1;
            LOAD(pr[ph], tn);
        }
    }

    if (write_tail){
        float* hp = out + (long long)TT*BB*8;
        hp[b*8 + q]         = h;
        hp[BB*8 + b*8 + q]  = c;
    }
}

// ---------------------------------------------------------------------------
extern "C" void kernel_launch(void* const* d_in, const int* in_sizes, int n_in,
                              void* d_out, int out_size)
{
    const float* x   = (const float*)d_in[0];
    const float* Wf  = (const float*)d_in[1];
    const float* bf  = (const float*)d_in[2];
    const float* Wi  = (const float*)d_in[3];
    const float* bi  = (const float*)d_in[4];
    const float* Wu  = (const float*)d_in[5];
    const float* bu  = (const float*)d_in[6];
    const float* Wo  = (const float*)d_in[7];
    const float* bo  = (const float*)d_in[8];
    const float* qwf = (const float*)d_in[9];
    const float* qwi = (const float*)d_in[10];
    // d_in[11] = qwu: unused — g path has no quantum gate in the reference
    const float* qwo = (const float*)d_in[12];
    float* out = (float*)d_out;

    const int write_tail = (out_size >= TT*BB*8 + 2*BB*8) ? 1 : 0;

    fused_kernel<<<PREPB + RECB, 256>>>(x, Wf, bf, Wi, bi, Wu, bu, Wo, bo,
                                        qwf, qwi, qwo, out, write_tail);
}